// round 3
// baseline (speedup 1.0000x reference)
#include <cuda_runtime.h>

#define IMG_H 480
#define IMG_W 640
#define IMG_HW (IMG_H * IMG_W)
#define OCH 64
#define KK 25            // 5x5
#define KP 26            // padded weight row (u64 elems) for aligned LDS.128 pairs
#define TKX 128          // tile width in pixels
#define TKY 4            // tile height in pixels
#define SW 132           // smem tile row width  (TKX + 4)
#define SH 8             // smem tile rows       (TKY + 4)
#define THREADS 256
#define THRESH 1e-4f

// ---- packed f32x2 helpers (Blackwell FFMA2 path, PTX-only) ----
__device__ __forceinline__ unsigned long long ffma2(unsigned long long a,
                                                    unsigned long long b,
                                                    unsigned long long c) {
    unsigned long long d;
    asm("fma.rn.f32x2 %0, %1, %2, %3;" : "=l"(d) : "l"(a), "l"(b), "l"(c));
    return d;
}
__device__ __forceinline__ unsigned long long pack2(float lo, float hi) {
    unsigned long long d;
    asm("mov.b64 %0, {%1, %2};" : "=l"(d) : "f"(lo), "f"(hi));
    return d;
}
__device__ __forceinline__ void unpack2(unsigned long long d, float& lo, float& hi) {
    asm("mov.b64 {%0, %1}, %2;" : "=f"(lo), "=f"(hi) : "l"(d));
}

__global__ __launch_bounds__(THREADS, 3)
void normdepthconv_kernel(const float* __restrict__ x,
                          const float* __restrict__ wt,
                          float* __restrict__ out) {
    __shared__ float tile[SH * SW];                            // 4224 B
    __shared__ __align__(16) unsigned long long w2s[OCH * KP]; // 13312 B, {w,w} pairs

    const int b  = blockIdx.z;
    const int X0 = blockIdx.x * TKX;
    const int Y0 = blockIdx.y * TKY;
    const int tid = threadIdx.x;

    // ---- cooperative halo-tile load (zero-padded borders) ----
    const float* xb = x + (size_t)b * IMG_HW;
    for (int i = tid; i < SH * SW; i += THREADS) {
        int r = i / SW;
        int c = i - r * SW;
        int gy = Y0 - 2 + r;
        int gx = X0 - 2 + c;
        float v = 0.f;
        if (gy >= 0 && gy < IMG_H && gx >= 0 && gx < IMG_W) v = xb[gy * IMG_W + gx];
        tile[i] = v;
    }
    // ---- weights, duplicated into both f32x2 halves, rows padded to KP ----
    for (int i = tid; i < OCH * KK; i += THREADS) {
        int o = i / KK;
        int k = i - o * KK;
        float w = wt[i];
        w2s[o * KP + k] = pack2(w, w);
    }
    __syncthreads();

    const int tx = tid & 63;     // 64 threads across x, 2 pixels each -> 128
    const int ty = tid >> 6;     // 4 rows
    const int c0 = 2 * tx;       // smem col of leftmost needed value (8B aligned)

    // ---- pass 1: box sums S and valid counts N for 2 pixels ----
    float S0 = 0.f, S1 = 0.f, N0 = 0.f, N1 = 0.f;
#pragma unroll
    for (int dy = 0; dy < 5; ++dy) {
        const float2* row = reinterpret_cast<const float2*>(&tile[(ty + dy) * SW + c0]);
        float2 p0 = row[0], p1 = row[1], p2 = row[2];
        float v[6] = {p0.x, p0.y, p1.x, p1.y, p2.x, p2.y};
#pragma unroll
        for (int kw = 0; kw < 5; ++kw) {
            float m0 = (v[kw]     > THRESH) ? 1.f : 0.f;
            float m1 = (v[kw + 1] > THRESH) ? 1.f : 0.f;
            S0 += v[kw];     N0 += m0;
            S1 += v[kw + 1]; N1 += m1;
        }
    }
    const float ref0 = S0 / (N0 + 1e-6f);
    const float ref1 = S1 / (N1 + 1e-6f);

    // ---- pass 2: packed t-vectors  t[k] = mask * (ref - v) ----
    unsigned long long ta[KK];   // {t(px0), t(px1)}
#pragma unroll
    for (int dy = 0; dy < 5; ++dy) {
        const float2* row = reinterpret_cast<const float2*>(&tile[(ty + dy) * SW + c0]);
        float2 p0 = row[0], p1 = row[1], p2 = row[2];
        float v[6] = {p0.x, p0.y, p1.x, p1.y, p2.x, p2.y};
#pragma unroll
        for (int kw = 0; kw < 5; ++kw) {
            const int k = dy * 5 + kw;
            float t0 = (v[kw]     > THRESH) ? (ref0 - v[kw])     : 0.f;
            float t1 = (v[kw + 1] > THRESH) ? (ref1 - v[kw + 1]) : 0.f;
            ta[k] = pack2(t0, t1);
        }
    }

    // ---- 64-channel packed GEMV, o unrolled x2 for dual FFMA2 chains ----
    float* outp = out + (size_t)b * OCH * IMG_HW + (size_t)(Y0 + ty) * IMG_W + (X0 + c0);
#pragma unroll 1
    for (int o = 0; o < OCH; o += 2) {
        const ulonglong2* wrA = reinterpret_cast<const ulonglong2*>(&w2s[o * KP]);
        const ulonglong2* wrB = reinterpret_cast<const ulonglong2*>(&w2s[(o + 1) * KP]);
        unsigned long long acc0 = 0ull;
        unsigned long long acc1 = 0ull;
#pragma unroll
        for (int kp = 0; kp < 12; ++kp) {          // k = 2*kp, 2*kp+1
            ulonglong2 wA = wrA[kp];
            ulonglong2 wB = wrB[kp];
            unsigned long long t0 = ta[2 * kp];
            unsigned long long t1 = ta[2 * kp + 1];
            acc0 = ffma2(wA.x, t0, acc0);
            acc1 = ffma2(wB.x, t0, acc1);
            acc0 = ffma2(wA.y, t1, acc0);
            acc1 = ffma2(wB.y, t1, acc1);
        }
        {
            unsigned long long t24 = ta[24];
            acc0 = ffma2(w2s[o * KP + 24],       t24, acc0);
            acc1 = ffma2(w2s[(o + 1) * KP + 24], t24, acc1);
        }
        float a0, a1, b0, b1;
        unpack2(acc0, a0, a1);
        unpack2(acc1, b0, b1);
        float* p = outp + (size_t)o * IMG_HW;
        *reinterpret_cast<float2*>(p)          = make_float2(a0, a1);
        *reinterpret_cast<float2*>(p + IMG_HW) = make_float2(b0, b1);
    }
}

extern "C" void kernel_launch(void* const* d_in, const int* in_sizes, int n_in,
                              void* d_out, int out_size) {
    const float* x = (const float*)d_in[0];
    const float* w = (const float*)d_in[1];
    if (n_in >= 2 && in_sizes[0] == OCH * KK) {   // defensive input-order check
        x = (const float*)d_in[1];
        w = (const float*)d_in[0];
    }
    dim3 grid(IMG_W / TKX, IMG_H / TKY, 8);   // 5 x 120 x 8 = 4800 CTAs
    normdepthconv_kernel<<<grid, THREADS>>>(x, w, (float*)d_out);
}

// round 4
// speedup vs baseline: 1.2761x; 1.2761x over previous
#include <cuda_runtime.h>

#define IMG_H 480
#define IMG_W 640
#define IMG_HW (IMG_H * IMG_W)
#define OCH 64
#define KK 25            // 5x5
#define WP 14            // u64 k-pairs per weight row (13 used + 1 zero pad), 112 B stride
#define TKX 128          // tile width in pixels
#define TKY 8            // tile height in pixels
#define SW 132           // smem tile row width  (TKX + 4)
#define SH 12            // smem tile rows       (TKY + 4)
#define THREADS 256
#define THRESH 1e-4f

// ---- packed f32x2 helpers (Blackwell FFMA2 path, PTX-only) ----
__device__ __forceinline__ unsigned long long ffma2(unsigned long long a,
                                                    unsigned long long b,
                                                    unsigned long long c) {
    unsigned long long d;
    asm("fma.rn.f32x2 %0, %1, %2, %3;" : "=l"(d) : "l"(a), "l"(b), "l"(c));
    return d;
}
__device__ __forceinline__ unsigned long long pack2(float lo, float hi) {
    unsigned long long d;
    asm("mov.b64 %0, {%1, %2};" : "=l"(d) : "f"(lo), "f"(hi));
    return d;
}
__device__ __forceinline__ float hfold(unsigned long long d) {   // lo + hi
    float lo, hi;
    asm("mov.b64 {%0, %1}, %2;" : "=f"(lo), "=f"(hi) : "l"(d));
    return lo + hi;
}

__global__ __launch_bounds__(THREADS, 2)
void normdepthconv_kernel(const float* __restrict__ x,
                          const float* __restrict__ wt,
                          float* __restrict__ out) {
    __shared__ float tile[SH * SW];                            // 6336 B
    __shared__ __align__(16) unsigned long long w2s[OCH * WP]; // 7168 B, {w2j,w2j+1} pairs

    const int b  = blockIdx.z;
    const int X0 = blockIdx.x * TKX;
    const int Y0 = blockIdx.y * TKY;
    const int tid = threadIdx.x;

    // ---- cooperative halo-tile load (zero-padded borders) ----
    const float* xb = x + (size_t)b * IMG_HW;
    for (int i = tid; i < SH * SW; i += THREADS) {
        int r = i / SW;
        int c = i - r * SW;
        int gy = Y0 - 2 + r;
        int gx = X0 - 2 + c;
        float v = 0.f;
        if (gy >= 0 && gy < IMG_H && gx >= 0 && gx < IMG_W) v = xb[gy * IMG_W + gx];
        tile[i] = v;
    }
    // ---- weights as k-pair u64s: {w[2j], w[2j+1]}, row padded to WP pairs ----
    for (int i = tid; i < OCH * WP; i += THREADS) {
        int o = i / WP;
        int j = i - o * WP;
        unsigned long long v;
        if (j < 12)       v = pack2(wt[o * KK + 2 * j], wt[o * KK + 2 * j + 1]);
        else if (j == 12) v = pack2(wt[o * KK + 24], 0.f);
        else              v = 0ull;
        w2s[i] = v;
    }
    __syncthreads();

    const int tx = tid & 31;     // 32 threads across x, 4 pixels each -> 128
    const int ty = tid >> 5;     // 8 rows
    const int c0 = 4 * tx;       // smem col of leftmost needed value (16B aligned)

    // ---- pass 1: box sums S and valid counts N for 4 pixels ----
    float S0 = 0.f, S1 = 0.f, S2 = 0.f, S3 = 0.f;
    float N0 = 0.f, N1 = 0.f, N2 = 0.f, N3 = 0.f;
#pragma unroll
    for (int dy = 0; dy < 5; ++dy) {
        const float4* row = reinterpret_cast<const float4*>(&tile[(ty + dy) * SW + c0]);
        float4 lo = row[0];
        float4 hi = row[1];
        float v[8] = {lo.x, lo.y, lo.z, lo.w, hi.x, hi.y, hi.z, hi.w};
#pragma unroll
        for (int kw = 0; kw < 5; ++kw) {
            S0 += v[kw];     N0 += (v[kw]     > THRESH) ? 1.f : 0.f;
            S1 += v[kw + 1]; N1 += (v[kw + 1] > THRESH) ? 1.f : 0.f;
            S2 += v[kw + 2]; N2 += (v[kw + 2] > THRESH) ? 1.f : 0.f;
            S3 += v[kw + 3]; N3 += (v[kw + 3] > THRESH) ? 1.f : 0.f;
        }
    }
    const float ref0 = S0 / (N0 + 1e-6f);
    const float ref1 = S1 / (N1 + 1e-6f);
    const float ref2 = S2 / (N2 + 1e-6f);
    const float ref3 = S3 / (N3 + 1e-6f);

    // ---- pass 2: per-pixel t packed along k: tp[px][j] = {t[2j], t[2j+1]} ----
    unsigned long long tp0[13], tp1[13], tp2[13], tp3[13];
    float pv0, pv1, pv2, pv3;                       // pending even-k values
#pragma unroll
    for (int dy = 0; dy < 5; ++dy) {
        const float4* row = reinterpret_cast<const float4*>(&tile[(ty + dy) * SW + c0]);
        float4 lo = row[0];
        float4 hi = row[1];
        float v[8] = {lo.x, lo.y, lo.z, lo.w, hi.x, hi.y, hi.z, hi.w};
#pragma unroll
        for (int kw = 0; kw < 5; ++kw) {
            const int k = dy * 5 + kw;
            float t0 = (v[kw]     > THRESH) ? (ref0 - v[kw])     : 0.f;
            float t1 = (v[kw + 1] > THRESH) ? (ref1 - v[kw + 1]) : 0.f;
            float t2 = (v[kw + 2] > THRESH) ? (ref2 - v[kw + 2]) : 0.f;
            float t3 = (v[kw + 3] > THRESH) ? (ref3 - v[kw + 3]) : 0.f;
            if (k & 1) {
                tp0[k >> 1] = pack2(pv0, t0);
                tp1[k >> 1] = pack2(pv1, t1);
                tp2[k >> 1] = pack2(pv2, t2);
                tp3[k >> 1] = pack2(pv3, t3);
            } else {
                pv0 = t0; pv1 = t1; pv2 = t2; pv3 = t3;
            }
        }
    }
    tp0[12] = pack2(pv0, 0.f);   // k = 24
    tp1[12] = pack2(pv1, 0.f);
    tp2[12] = pack2(pv2, 0.f);
    tp3[12] = pack2(pv3, 0.f);

    // ---- 64-channel GEMV: LDS.128 = 4 distinct weights, 4 FFMA2 chains ----
    float* outp = out + (size_t)b * OCH * IMG_HW + (size_t)(Y0 + ty) * IMG_W + (X0 + c0);
#pragma unroll 2
    for (int o = 0; o < OCH; ++o) {
        const unsigned long long* wrow = &w2s[o * WP];
        const ulonglong2* wr2 = reinterpret_cast<const ulonglong2*>(wrow);
        unsigned long long a0 = 0ull, a1 = 0ull, a2 = 0ull, a3 = 0ull;
#pragma unroll
        for (int j = 0; j < 6; ++j) {              // k-pairs 2j, 2j+1  (0..11)
            ulonglong2 w = wr2[j];
            a0 = ffma2(w.x, tp0[2 * j], a0);
            a1 = ffma2(w.x, tp1[2 * j], a1);
            a2 = ffma2(w.x, tp2[2 * j], a2);
            a3 = ffma2(w.x, tp3[2 * j], a3);
            a0 = ffma2(w.y, tp0[2 * j + 1], a0);
            a1 = ffma2(w.y, tp1[2 * j + 1], a1);
            a2 = ffma2(w.y, tp2[2 * j + 1], a2);
            a3 = ffma2(w.y, tp3[2 * j + 1], a3);
        }
        {
            unsigned long long w12 = wrow[12];     // {w24, 0}
            a0 = ffma2(w12, tp0[12], a0);
            a1 = ffma2(w12, tp1[12], a1);
            a2 = ffma2(w12, tp2[12], a2);
            a3 = ffma2(w12, tp3[12], a3);
        }
        *reinterpret_cast<float4*>(outp + (size_t)o * IMG_HW) =
            make_float4(hfold(a0), hfold(a1), hfold(a2), hfold(a3));
    }
}

extern "C" void kernel_launch(void* const* d_in, const int* in_sizes, int n_in,
                              void* d_out, int out_size) {
    const float* x = (const float*)d_in[0];
    const float* w = (const float*)d_in[1];
    if (n_in >= 2 && in_sizes[0] == OCH * KK) {   // defensive input-order check
        x = (const float*)d_in[1];
        w = (const float*)d_in[0];
    }
    dim3 grid(IMG_W / TKX, IMG_H / TKY, 8);   // 5 x 60 x 8 = 2400 CTAs
    normdepthconv_kernel<<<grid, THREADS>>>(x, w, (float*)d_out);
}